// round 5
// baseline (speedup 1.0000x reference)
#include <cuda_runtime.h>
#include <cuda_bf16.h>
#include <cstdint>

#define NN      50000
#define NE      400000
#define NG      128
#define IN_DIM  768
#define HID     128
#define NCLS    11
#define BN_EPS  1e-5f

// ---------------- scratch (device globals; no allocation allowed) ----------------
__device__ float    g_y[(size_t)NN * 256];      // [NN,256]: cols 0..127 = agg-side, 128..255 = self-side
__device__ float    g_hpre[(size_t)NN * HID];   // pre-BN activations
__device__ float    g_h[(size_t)NN * HID];      // post-BN layer-3 activations (fp32, for pool)
__device__ __align__(16) __nv_bfloat16 g_ahi[(size_t)NN * IN_DIM];  // activation hi (K=768 or 128)
__device__ __align__(16) __nv_bfloat16 g_alo[(size_t)NN * IN_DIM];  // activation lo
__device__ __align__(16) __nv_bfloat16 g_whi[256 * IN_DIM];         // fused [Wl;Wr] hi
__device__ __align__(16) __nv_bfloat16 g_wlo[256 * IN_DIM];         // fused [Wl;Wr] lo
__device__ int      g_deg[NN];
__device__ int      g_start[NN];
__device__ int      g_cursor[NN];
__device__ int      g_total;
__device__ int      g_csr[NE];                  // src ids bucketed by dst (unordered buckets)
__device__ float    g_part[256 * 256];          // bn partials
__device__ unsigned g_pool[NG * HID];           // order-preserving-encoded max

// ---------------- helpers ----------------
__device__ __forceinline__ uint32_t smem_u32(const void* p) {
    uint32_t a;
    asm("{ .reg .u64 t; cvta.to.shared.u64 t, %1; cvt.u32.u64 %0, t; }" : "=r"(a) : "l"(p));
    return a;
}
__device__ __forceinline__ unsigned fenc(float f) {
    unsigned u = __float_as_uint(f);
    return (u >> 31) ? ~u : (u | 0x80000000u);
}
__device__ __forceinline__ float fdec(unsigned e) {
    return (e >> 31) ? __uint_as_float(e & 0x7fffffffu) : __uint_as_float(~e);
}

#define LDMX4(d, a)                                                                  \
    asm volatile("ldmatrix.sync.aligned.m8n8.x4.shared.b16 {%0,%1,%2,%3}, [%4];"     \
        : "=r"((d)[0]), "=r"((d)[1]), "=r"((d)[2]), "=r"((d)[3]) : "r"(a))

#define CPASYNC16(dst, src) \
    asm volatile("cp.async.cg.shared.global [%0], [%1], 16;" :: "r"(dst), "l"(src) : "memory")
#define CPASYNC16Z(dst, src, sz) \
    asm volatile("cp.async.cg.shared.global [%0], [%1], 16, %2;" :: "r"(dst), "l"(src), "r"(sz) : "memory")
#define CPCOMMIT() asm volatile("cp.async.commit_group;" ::: "memory")
#define CPWAIT0()  asm volatile("cp.async.wait_group 0;" ::: "memory")

__device__ __forceinline__ void mma16816(float* c, const uint32_t* a, const uint32_t* b) {
    asm volatile(
        "mma.sync.aligned.m16n8k16.row.col.f32.bf16.bf16.f32 "
        "{%0,%1,%2,%3}, {%4,%5,%6,%7}, {%8,%9}, {%0,%1,%2,%3};"
        : "+f"(c[0]), "+f"(c[1]), "+f"(c[2]), "+f"(c[3])
        : "r"(a[0]), "r"(a[1]), "r"(a[2]), "r"(a[3]), "r"(b[0]), "r"(b[1]));
}

__device__ __forceinline__ void split_bf16(float v, __nv_bfloat16& hi, __nv_bfloat16& lo) {
    hi = __float2bfloat16(v);
    lo = __float2bfloat16(v - __bfloat162float(hi));
}

// ---------------- CSR build ----------------
__global__ void zero_deg_k() {
    int i = blockIdx.x * blockDim.x + threadIdx.x;
    if (i < NN) g_deg[i] = 0;
    if (i == 0) g_total = 0;
}

__global__ void hist_k(const int* __restrict__ dst) {
    int e = blockIdx.x * blockDim.x + threadIdx.x;
    if (e < NE) atomicAdd(&g_deg[dst[e]], 1);
}

// warp-aggregated offset allocation (bucket order irrelevant for the gather)
__global__ void alloc_off_k() {
    int i = blockIdx.x * blockDim.x + threadIdx.x;
    int lane = threadIdx.x & 31;
    int d = (i < NN) ? g_deg[i] : 0;
    int inc = d;
    #pragma unroll
    for (int s = 1; s < 32; s <<= 1) {
        int v = __shfl_up_sync(0xffffffffu, inc, s);
        if (lane >= s) inc += v;
    }
    int ex  = inc - d;
    int tot = __shfl_sync(0xffffffffu, inc, 31);
    int base = 0;
    if (lane == 31) base = atomicAdd(&g_total, tot);
    base = __shfl_sync(0xffffffffu, base, 31);
    if (i < NN) { g_start[i] = base + ex; g_cursor[i] = base + ex; }
}

__global__ void fill_k(const int* __restrict__ src, const int* __restrict__ dst) {
    int e = blockIdx.x * blockDim.x + threadIdx.x;
    if (e < NE) {
        int p = atomicAdd(&g_cursor[dst[e]], 1);
        g_csr[p] = src[e];
    }
}

// ---------------- conversions ----------------
__global__ void convert_w_k(const float* __restrict__ Wl, const float* __restrict__ Wr, int K) {
    int idx = blockIdx.x * blockDim.x + threadIdx.x;
    if (idx >= 256 * K) return;
    int row = idx / K, col = idx - row * K;
    float v = (row < 128) ? Wl[row * K + col] : Wr[(row - 128) * K + col];
    __nv_bfloat16 hi, lo;
    split_bf16(v, hi, lo);
    g_whi[idx] = hi;
    g_wlo[idx] = lo;
}

// x (fp32 [NN,768]) -> g_ahi/g_alo (bf16)
__global__ void conv_x_k(const float* __restrict__ x) {
    size_t i = (size_t)(blockIdx.x * blockDim.x + threadIdx.x) * 4;
    if (i >= (size_t)NN * IN_DIM) return;
    float4 v = *reinterpret_cast<const float4*>(x + i);
    __nv_bfloat16 h0, h1, h2, h3, l0, l1, l2, l3;
    split_bf16(v.x, h0, l0); split_bf16(v.y, h1, l1);
    split_bf16(v.z, h2, l2); split_bf16(v.w, h3, l3);
    __nv_bfloat162 hp0 = __halves2bfloat162(h0, h1), hp1 = __halves2bfloat162(h2, h3);
    __nv_bfloat162 lp0 = __halves2bfloat162(l0, l1), lp1 = __halves2bfloat162(l2, l3);
    *reinterpret_cast<uint2*>(g_ahi + i) = make_uint2(*(uint32_t*)&hp0, *(uint32_t*)&hp1);
    *reinterpret_cast<uint2*>(g_alo + i) = make_uint2(*(uint32_t*)&lp0, *(uint32_t*)&lp1);
}

// ---------------- tensor-core GEMM (pre-split bf16, all-cp.async, double-buffered) ----------------
// Y[M,256] = A[M,K] @ W[256,K]^T as Ahi@Whi + Ahi@Wlo + Alo@Whi.
// BM=128, BN=128 (gridDim.y=2), BK=32. 8 warps (4M x 2N), warp tile 32x64.
// Padded rows: 40 bf16 (80 B) -> conflict-free ldmatrix; 16B cp.async chunks.
#define PADK  40
#define ASUB  10240                 // one sub-buffer: 128 rows * 80 B
#define BUFB  40960                 // Ah Al Bh Bl
#define GEMM_SMEM (2 * BUFB)

__global__ __launch_bounds__(256)
void gemm_mma(int M, int K) {
    extern __shared__ char dsm[];
    const uint32_t sm0 = smem_u32(dsm);

    const int tid  = threadIdx.x;
    const int lane = tid & 31;
    const int wid  = tid >> 5;
    const int wm   = wid & 3;            // 4 warps in M
    const int wn   = wid >> 2;           // 2 warps in N
    const int row0 = blockIdx.x * 128;
    const int n0g  = blockIdx.y * 128;

    // per-lane ldmatrix byte offsets within a sub-buffer
    const int a_row = lane & 15;
    const int a_kh  = (lane >> 4) * 8;
    const uint32_t aoff = (uint32_t)(((wm * 32 + a_row) * PADK + a_kh) * 2);
    const int b_row = ((lane >> 4) << 3) + (lane & 7);
    const int b_kh  = ((lane >> 3) & 1) * 8;
    const uint32_t boff = (uint32_t)(((wn * 64 + b_row) * PADK + b_kh) * 2);

    float acc[2][8][4];
    #pragma unroll
    for (int i = 0; i < 2; i++)
        #pragma unroll
        for (int j = 0; j < 8; j++)
            #pragma unroll
            for (int q = 0; q < 4; q++) acc[i][j][q] = 0.f;

    const int ntiles = K / 32;

    auto fill = [&](int t) {
        const int k0 = t * 32;
        const uint32_t base = sm0 + (uint32_t)(t & 1) * BUFB;
        // A hi/lo: 128 rows x 4 chunks (16B each)
        #pragma unroll
        for (int i = 0; i < 2; i++) {
            int s   = tid + 256 * i;     // 0..511
            int r   = s >> 2;
            int seg = s & 3;
            uint32_t off = (uint32_t)(r * (PADK * 2) + seg * 16);
            size_t go = (size_t)(row0 + r) * K + k0 + seg * 8;
            int sz = (row0 + r < M) ? 16 : 0;
            CPASYNC16Z(base + off,        (const void*)(g_ahi + go), sz);
            CPASYNC16Z(base + ASUB + off, (const void*)(g_alo + go), sz);
        }
        // B hi/lo: 128 rows x 4 chunks
        #pragma unroll
        for (int i = 0; i < 2; i++) {
            int s   = tid + 256 * i;
            int r   = s >> 2;
            int seg = s & 3;
            uint32_t off = (uint32_t)(r * (PADK * 2) + seg * 16);
            size_t go = (size_t)(n0g + r) * K + k0 + seg * 8;
            CPASYNC16(base + 2 * ASUB + off, (const void*)(g_whi + go));
            CPASYNC16(base + 3 * ASUB + off, (const void*)(g_wlo + go));
        }
        CPCOMMIT();
    };

    fill(0);
    for (int t = 0; t < ntiles; t++) {
        CPWAIT0();
        __syncthreads();
        if (t + 1 < ntiles) fill(t + 1);

        const uint32_t base = sm0 + (uint32_t)(t & 1) * BUFB;
        const uint32_t pAh = base + aoff, pAl = base + ASUB + aoff;
        const uint32_t pBh = base + 2 * ASUB + boff, pBl = base + 3 * ASUB + boff;
        #pragma unroll
        for (int ks = 0; ks < 2; ks++) {
            const uint32_t ko = (uint32_t)(ks * 32);          // 16 cols * 2B
            uint32_t ah[2][4], al[2][4];
            LDMX4(ah[0], pAh + ko);
            LDMX4(ah[1], pAh + ko + 16 * PADK * 2);           // +16 rows
            LDMX4(al[0], pAl + ko);
            LDMX4(al[1], pAl + ko + 16 * PADK * 2);
            #pragma unroll
            for (int p = 0; p < 4; p++) {
                uint32_t bh[4], bl[4];
                LDMX4(bh, pBh + ko + (uint32_t)(p * 16 * PADK * 2));
                LDMX4(bl, pBl + ko + (uint32_t)(p * 16 * PADK * 2));
                #pragma unroll
                for (int q = 0; q < 2; q++) {
                    const int nt = 2 * p + q;
                    uint32_t bqh[2] = { bh[2 * q], bh[2 * q + 1] };
                    uint32_t bql[2] = { bl[2 * q], bl[2 * q + 1] };
                    mma16816(acc[0][nt], ah[0], bqh);
                    mma16816(acc[0][nt], ah[0], bql);
                    mma16816(acc[0][nt], al[0], bqh);
                    mma16816(acc[1][nt], ah[1], bqh);
                    mma16816(acc[1][nt], ah[1], bql);
                    mma16816(acc[1][nt], al[1], bqh);
                }
            }
        }
        __syncthreads();
    }

    // ---- store C ----
    const int g   = lane >> 2;
    const int tig = lane & 3;
    #pragma unroll
    for (int mt = 0; mt < 2; mt++) {
        #pragma unroll
        for (int nt = 0; nt < 8; nt++) {
            int r = row0 + wm * 32 + mt * 16 + g;
            int c = n0g + wn * 64 + nt * 8 + 2 * tig;
            if (r < M)
                *reinterpret_cast<float2*>(&g_y[(size_t)r * 256 + c]) =
                    make_float2(acc[mt][nt][0], acc[mt][nt][1]);
            if (r + 8 < M)
                *reinterpret_cast<float2*>(&g_y[(size_t)(r + 8) * 256 + c]) =
                    make_float2(acc[mt][nt][2], acc[mt][nt][3]);
        }
    }
}

// ---------------- gather (bucketed) + combine ----------------
__global__ void gather_combine(const float* __restrict__ bias) {
    int warp = (blockIdx.x * blockDim.x + threadIdx.x) >> 5;
    int lane = threadIdx.x & 31;
    if (warp >= NN) return;
    int e0 = g_start[warp];
    int deg = g_deg[warp];
    int e1 = e0 + deg;
    float4 a0 = make_float4(0.f, 0.f, 0.f, 0.f);
    float4 a1 = make_float4(0.f, 0.f, 0.f, 0.f);
    float4 a2 = make_float4(0.f, 0.f, 0.f, 0.f);
    float4 a3 = make_float4(0.f, 0.f, 0.f, 0.f);
    int e = e0;
    for (; e + 4 <= e1; e += 4) {
        int s0 = g_csr[e], s1 = g_csr[e + 1], s2 = g_csr[e + 2], s3 = g_csr[e + 3];
        float4 v0 = reinterpret_cast<const float4*>(g_y + (size_t)s0 * 256)[lane];
        float4 v1 = reinterpret_cast<const float4*>(g_y + (size_t)s1 * 256)[lane];
        float4 v2 = reinterpret_cast<const float4*>(g_y + (size_t)s2 * 256)[lane];
        float4 v3 = reinterpret_cast<const float4*>(g_y + (size_t)s3 * 256)[lane];
        a0.x += v0.x; a0.y += v0.y; a0.z += v0.z; a0.w += v0.w;
        a1.x += v1.x; a1.y += v1.y; a1.z += v1.z; a1.w += v1.w;
        a2.x += v2.x; a2.y += v2.y; a2.z += v2.z; a2.w += v2.w;
        a3.x += v3.x; a3.y += v3.y; a3.z += v3.z; a3.w += v3.w;
    }
    for (; e < e1; e++) {
        int s = g_csr[e];
        float4 v = reinterpret_cast<const float4*>(g_y + (size_t)s * 256)[lane];
        a0.x += v.x; a0.y += v.y; a0.z += v.z; a0.w += v.w;
    }
    float4 acc;
    acc.x = (a0.x + a1.x) + (a2.x + a3.x);
    acc.y = (a0.y + a1.y) + (a2.y + a3.y);
    acc.z = (a0.z + a1.z) + (a2.z + a3.z);
    acc.w = (a0.w + a1.w) + (a2.w + a3.w);
    float invd = 1.f / fmaxf((float)deg, 1.f);
    float4 r  = reinterpret_cast<const float4*>(g_y + (size_t)warp * 256 + 128)[lane];
    float4 b4 = reinterpret_cast<const float4*>(bias)[lane];
    float4 o;
    o.x = acc.x * invd + r.x + b4.x;
    o.y = acc.y * invd + r.y + b4.y;
    o.z = acc.z * invd + r.z + b4.z;
    o.w = acc.w * invd + r.w + b4.w;
    reinterpret_cast<float4*>(g_hpre + (size_t)warp * HID)[lane] = o;
}

// ---------------- BatchNorm ----------------
__global__ void bn_stats_k() {       // 256 blocks, no atomics / no zeroing
    int f = threadIdx.x;             // 128
    float s = 0.f, s2 = 0.f;
    for (int r = blockIdx.x; r < NN; r += 256) {
        float v = g_hpre[(size_t)r * HID + f];
        s += v; s2 += v * v;
    }
    g_part[blockIdx.x * 256 + f]       = s;
    g_part[blockIdx.x * 256 + 128 + f] = s2;
}

// mode 0: relu + write bf16 hi/lo (feeds next GEMM); mode 1: plain + write fp32 g_h (feeds pool)
__global__ void bn_norm_k(const float* __restrict__ gamma, const float* __restrict__ beta,
                          int mode) {
    int f = threadIdx.x;
    float s = 0.f, s2 = 0.f;
    #pragma unroll 4
    for (int b = 0; b < 256; b++) {
        s  += g_part[b * 256 + f];
        s2 += g_part[b * 256 + 128 + f];
    }
    float mean = s * (1.f / NN);
    float var  = s2 * (1.f / NN) - mean * mean;
    float rstd = rsqrtf(var + BN_EPS);
    float g = gamma[f] * rstd;
    float b = beta[f] - mean * g;
    for (int r = blockIdx.x; r < NN; r += gridDim.x) {
        float v = g_hpre[(size_t)r * HID + f] * g + b;
        if (mode == 0) {
            v = fmaxf(v, 0.f);
            __nv_bfloat16 hi, lo;
            split_bf16(v, hi, lo);
            g_ahi[(size_t)r * HID + f] = hi;
            g_alo[(size_t)r * HID + f] = lo;
        } else {
            g_h[(size_t)r * HID + f] = v;
        }
    }
}

// ---------------- global max pool (batch is sorted) ----------------
__global__ void pool_init_k() {
    g_pool[blockIdx.x * HID + threadIdx.x] = 0x007fffffu;  // fenc(-inf)
}

#define POOL_CHUNK 512
__global__ void pool_max_k(const int* __restrict__ batch) {
    int f = threadIdx.x;  // 128
    int r0 = blockIdx.x * POOL_CHUNK;
    int r1 = min(r0 + POOL_CHUNK, NN);
    int cur = -1;
    float m = -3.4e38f;
    for (int r = r0; r < r1; r++) {
        int gi = batch[r];
        if (gi != cur) {
            if (cur >= 0) atomicMax(&g_pool[cur * HID + f], fenc(m));
            cur = gi;
            m = -3.4e38f;
        }
        m = fmaxf(m, g_h[(size_t)r * HID + f]);
    }
    if (cur >= 0) atomicMax(&g_pool[cur * HID + f], fenc(m));
}

// ---------------- final linear ----------------
__global__ void final_linear_k(const float* __restrict__ Wlin, const float* __restrict__ blin,
                               float* __restrict__ out) {
    __shared__ float sh[HID];
    int g = blockIdx.x, t = threadIdx.x;
    sh[t] = fdec(g_pool[g * HID + t]);
    __syncthreads();
    if (t < NCLS) {
        float a = blin[t];
        #pragma unroll 8
        for (int k = 0; k < HID; k++) a += sh[k] * Wlin[t * HID + k];
        out[g * NCLS + t] = a;
    }
}

// ---------------- launch ----------------
extern "C" void kernel_launch(void* const* d_in, const int* in_sizes, int n_in,
                              void* d_out, int out_size) {
    const float* x    = (const float*)d_in[0];
    const int*   src  = (const int*)d_in[1];
    const int*   dst  = src + NE;
    const int*   batch = (const int*)d_in[2];
    const float* W1l = (const float*)d_in[3];
    const float* b1  = (const float*)d_in[4];
    const float* W1r = (const float*)d_in[5];
    const float* g1  = (const float*)d_in[6];
    const float* be1 = (const float*)d_in[7];
    const float* W2l = (const float*)d_in[8];
    const float* b2  = (const float*)d_in[9];
    const float* W2r = (const float*)d_in[10];
    const float* g2  = (const float*)d_in[11];
    const float* be2 = (const float*)d_in[12];
    const float* W3l = (const float*)d_in[13];
    const float* b3  = (const float*)d_in[14];
    const float* W3r = (const float*)d_in[15];
    const float* g3  = (const float*)d_in[16];
    const float* be3 = (const float*)d_in[17];
    const float* Wlin = (const float*)d_in[18];
    const float* blin = (const float*)d_in[19];
    float* out = (float*)d_out;

    cudaFuncSetAttribute(gemm_mma, cudaFuncAttributeMaxDynamicSharedMemorySize, GEMM_SMEM);

    const int mblocks = (NN + 127) / 128;          // 391
    const dim3 ggrid(mblocks, 2);
    const int gwarps  = (NN * 32 + 255) / 256;

    // ----- prologue + layer-1 GEMM first (so ncu's fixed capture slot lands on the GEMM) -----
    convert_w_k<<<(256 * IN_DIM + 255) / 256, 256>>>(W1l, W1r, IN_DIM);      // launch 1
    conv_x_k<<<(NN * IN_DIM / 4 + 255) / 256, 256>>>(x);                     // launch 2
    zero_deg_k<<<(NN + 255) / 256, 256>>>();                                 // launch 3
    gemm_mma<<<ggrid, 256, GEMM_SMEM>>>(NN, IN_DIM);                         // launch 4 (profiled)

    // CSR build (independent of GEMM)
    hist_k<<<(NE + 255) / 256, 256>>>(dst);
    alloc_off_k<<<(NN + 255) / 256, 256>>>();
    fill_k<<<(NE + 255) / 256, 256>>>(src, dst);

    // ----- layer 1 tail -----
    gather_combine<<<gwarps, 256>>>(b1);
    bn_stats_k<<<256, 128>>>();
    bn_norm_k<<<512, 128>>>(g1, be1, 0);

    // ----- layer 2 (K = 128) -----
    convert_w_k<<<(256 * HID + 255) / 256, 256>>>(W2l, W2r, HID);
    gemm_mma<<<ggrid, 256, GEMM_SMEM>>>(NN, HID);
    gather_combine<<<gwarps, 256>>>(b2);
    bn_stats_k<<<256, 128>>>();
    bn_norm_k<<<512, 128>>>(g2, be2, 0);

    // ----- layer 3 (K = 128, no relu, fp32 out) -----
    convert_w_k<<<(256 * HID + 255) / 256, 256>>>(W3l, W3r, HID);
    gemm_mma<<<ggrid, 256, GEMM_SMEM>>>(NN, HID);
    gather_combine<<<gwarps, 256>>>(b3);
    bn_stats_k<<<256, 128>>>();
    bn_norm_k<<<512, 128>>>(g3, be3, 1);

    // ----- pool + head -----
    pool_init_k<<<NG, HID>>>();
    pool_max_k<<<(NN + POOL_CHUNK - 1) / POOL_CHUNK, 128>>>(batch);
    final_linear_k<<<NG, HID>>>(Wlin, blin, out);
}

// round 6
// speedup vs baseline: 1.0055x; 1.0055x over previous
#include <cuda_runtime.h>
#include <cuda_bf16.h>
#include <cstdint>

#define NN      50000
#define NE      400000
#define NG      128
#define IN_DIM  768
#define HID     128
#define NCLS    11
#define BN_EPS  1e-5f

// ---------------- scratch (device globals; no allocation allowed) ----------------
__device__ float    g_y[(size_t)NN * 256];      // [NN,256]: cols 0..127 = agg-side, 128..255 = self-side
__device__ float    g_hpre[(size_t)NN * HID];   // pre-BN activations
__device__ float    g_h[(size_t)NN * HID];      // post-BN layer-3 activations (fp32, for pool)
__device__ __align__(16) __nv_bfloat16 g_ahi[(size_t)NN * IN_DIM];  // activation hi (K=768 or 128)
__device__ __align__(16) __nv_bfloat16 g_alo[(size_t)NN * IN_DIM];  // activation lo
__device__ __align__(16) __nv_bfloat16 g_whi[256 * IN_DIM];         // fused [Wl;Wr] hi
__device__ __align__(16) __nv_bfloat16 g_wlo[256 * IN_DIM];         // fused [Wl;Wr] lo
__device__ int      g_deg[NN];
__device__ int      g_start[NN];
__device__ int      g_cursor[NN];
__device__ int      g_total;
__device__ int      g_csr[NE];                  // src ids bucketed by dst (unordered buckets)
__device__ float    g_part[256 * 256];          // bn partials
__device__ unsigned g_pool[NG * HID];           // order-preserving-encoded max

// ---------------- helpers ----------------
__device__ __forceinline__ uint32_t smem_u32(const void* p) {
    uint32_t a;
    asm("{ .reg .u64 t; cvta.to.shared.u64 t, %1; cvt.u32.u64 %0, t; }" : "=r"(a) : "l"(p));
    return a;
}
__device__ __forceinline__ unsigned fenc(float f) {
    unsigned u = __float_as_uint(f);
    return (u >> 31) ? ~u : (u | 0x80000000u);
}
__device__ __forceinline__ float fdec(unsigned e) {
    return (e >> 31) ? __uint_as_float(e & 0x7fffffffu) : __uint_as_float(~e);
}

#define LDMX4(d, a)                                                                  \
    asm volatile("ldmatrix.sync.aligned.m8n8.x4.shared.b16 {%0,%1,%2,%3}, [%4];"     \
        : "=r"((d)[0]), "=r"((d)[1]), "=r"((d)[2]), "=r"((d)[3]) : "r"(a))

#define CPASYNC16(dst, src) \
    asm volatile("cp.async.cg.shared.global [%0], [%1], 16;" :: "r"(dst), "l"(src) : "memory")
#define CPASYNC16Z(dst, src, sz) \
    asm volatile("cp.async.cg.shared.global [%0], [%1], 16, %2;" :: "r"(dst), "l"(src), "r"(sz) : "memory")
#define CPCOMMIT() asm volatile("cp.async.commit_group;" ::: "memory")
#define CPWAIT0()  asm volatile("cp.async.wait_group 0;" ::: "memory")

__device__ __forceinline__ void mma16816(float* c, const uint32_t* a, const uint32_t* b) {
    asm volatile(
        "mma.sync.aligned.m16n8k16.row.col.f32.bf16.bf16.f32 "
        "{%0,%1,%2,%3}, {%4,%5,%6,%7}, {%8,%9}, {%0,%1,%2,%3};"
        : "+f"(c[0]), "+f"(c[1]), "+f"(c[2]), "+f"(c[3])
        : "r"(a[0]), "r"(a[1]), "r"(a[2]), "r"(a[3]), "r"(b[0]), "r"(b[1]));
}

__device__ __forceinline__ void split_bf16(float v, __nv_bfloat16& hi, __nv_bfloat16& lo) {
    hi = __float2bfloat16(v);
    lo = __float2bfloat16(v - __bfloat162float(hi));
}

// ---------------- CSR build ----------------
__global__ void zero_deg_k() {
    int i = blockIdx.x * blockDim.x + threadIdx.x;
    if (i < NN) g_deg[i] = 0;
    if (i == 0) g_total = 0;
}

__global__ void hist_k(const int* __restrict__ dst) {
    int e = blockIdx.x * blockDim.x + threadIdx.x;
    if (e < NE) atomicAdd(&g_deg[dst[e]], 1);
}

// warp-aggregated offset allocation (bucket order irrelevant for the gather)
__global__ void alloc_off_k() {
    int i = blockIdx.x * blockDim.x + threadIdx.x;
    int lane = threadIdx.x & 31;
    int d = (i < NN) ? g_deg[i] : 0;
    int inc = d;
    #pragma unroll
    for (int s = 1; s < 32; s <<= 1) {
        int v = __shfl_up_sync(0xffffffffu, inc, s);
        if (lane >= s) inc += v;
    }
    int ex  = inc - d;
    int tot = __shfl_sync(0xffffffffu, inc, 31);
    int base = 0;
    if (lane == 31) base = atomicAdd(&g_total, tot);
    base = __shfl_sync(0xffffffffu, base, 31);
    if (i < NN) { g_start[i] = base + ex; g_cursor[i] = base + ex; }
}

__global__ void fill_k(const int* __restrict__ src, const int* __restrict__ dst) {
    int e = blockIdx.x * blockDim.x + threadIdx.x;
    if (e < NE) {
        int p = atomicAdd(&g_cursor[dst[e]], 1);
        g_csr[p] = src[e];
    }
}

// ---------------- conversions ----------------
__global__ void convert_w_k(const float* __restrict__ Wl, const float* __restrict__ Wr, int K) {
    int idx = blockIdx.x * blockDim.x + threadIdx.x;
    if (idx >= 256 * K) return;
    int row = idx / K, col = idx - row * K;
    float v = (row < 128) ? Wl[row * K + col] : Wr[(row - 128) * K + col];
    __nv_bfloat16 hi, lo;
    split_bf16(v, hi, lo);
    g_whi[idx] = hi;
    g_wlo[idx] = lo;
}

// x (fp32 [NN,768]) -> g_ahi/g_alo (bf16)
__global__ void conv_x_k(const float* __restrict__ x) {
    size_t i = (size_t)(blockIdx.x * blockDim.x + threadIdx.x) * 4;
    if (i >= (size_t)NN * IN_DIM) return;
    float4 v = *reinterpret_cast<const float4*>(x + i);
    __nv_bfloat16 h0, h1, h2, h3, l0, l1, l2, l3;
    split_bf16(v.x, h0, l0); split_bf16(v.y, h1, l1);
    split_bf16(v.z, h2, l2); split_bf16(v.w, h3, l3);
    __nv_bfloat162 hp0 = __halves2bfloat162(h0, h1), hp1 = __halves2bfloat162(h2, h3);
    __nv_bfloat162 lp0 = __halves2bfloat162(l0, l1), lp1 = __halves2bfloat162(l2, l3);
    *reinterpret_cast<uint2*>(g_ahi + i) = make_uint2(*(uint32_t*)&hp0, *(uint32_t*)&hp1);
    *reinterpret_cast<uint2*>(g_alo + i) = make_uint2(*(uint32_t*)&lp0, *(uint32_t*)&lp1);
}

// ---------------- tensor-core GEMM (pre-split bf16, all-cp.async, double-buffered) ----------------
// Y[M,256] = A[M,K] @ W[256,K]^T as Ahi@Whi + Ahi@Wlo + Alo@Whi.
// 1D grid, paired blocks: row_tile = bx>>1, nhalf = bx&1 -> co-scheduled pairs share
// the A tile through L2 (halves A DRAM traffic vs the old (x, y) grid).
// BM=128, BN=128, BK=32. 8 warps (4M x 2N), warp tile 32x64.
// Padded rows: 40 bf16 (80 B) -> conflict-free ldmatrix; 16B cp.async chunks.
#define PADK  40
#define ASUB  10240                 // one sub-buffer: 128 rows * 80 B
#define BUFB  40960                 // Ah Al Bh Bl
#define GEMM_SMEM (2 * BUFB)

__global__ __launch_bounds__(256)
void gemm_mma(int M, int K) {
    extern __shared__ char dsm[];
    const uint32_t sm0 = smem_u32(dsm);

    const int tid  = threadIdx.x;
    const int lane = tid & 31;
    const int wid  = tid >> 5;
    const int wm   = wid & 3;            // 4 warps in M
    const int wn   = wid >> 2;           // 2 warps in N
    const int row0 = (blockIdx.x >> 1) * 128;
    const int n0g  = (blockIdx.x & 1) * 128;

    // per-lane ldmatrix byte offsets within a sub-buffer
    const int a_row = lane & 15;
    const int a_kh  = (lane >> 4) * 8;
    const uint32_t aoff = (uint32_t)(((wm * 32 + a_row) * PADK + a_kh) * 2);
    const int b_row = ((lane >> 4) << 3) + (lane & 7);
    const int b_kh  = ((lane >> 3) & 1) * 8;
    const uint32_t boff = (uint32_t)(((wn * 64 + b_row) * PADK + b_kh) * 2);

    float acc[2][8][4];
    #pragma unroll
    for (int i = 0; i < 2; i++)
        #pragma unroll
        for (int j = 0; j < 8; j++)
            #pragma unroll
            for (int q = 0; q < 4; q++) acc[i][j][q] = 0.f;

    const int ntiles = K / 32;

    auto fill = [&](int t) {
        const int k0 = t * 32;
        const uint32_t base = sm0 + (uint32_t)(t & 1) * BUFB;
        #pragma unroll
        for (int i = 0; i < 2; i++) {
            int s   = tid + 256 * i;     // 0..511
            int r   = s >> 2;
            int seg = s & 3;
            uint32_t off = (uint32_t)(r * (PADK * 2) + seg * 16);
            size_t go = (size_t)(row0 + r) * K + k0 + seg * 8;
            int sz = (row0 + r < M) ? 16 : 0;
            CPASYNC16Z(base + off,        (const void*)(g_ahi + go), sz);
            CPASYNC16Z(base + ASUB + off, (const void*)(g_alo + go), sz);
        }
        #pragma unroll
        for (int i = 0; i < 2; i++) {
            int s   = tid + 256 * i;
            int r   = s >> 2;
            int seg = s & 3;
            uint32_t off = (uint32_t)(r * (PADK * 2) + seg * 16);
            size_t go = (size_t)(n0g + r) * K + k0 + seg * 8;
            CPASYNC16(base + 2 * ASUB + off, (const void*)(g_whi + go));
            CPASYNC16(base + 3 * ASUB + off, (const void*)(g_wlo + go));
        }
        CPCOMMIT();
    };

    fill(0);
    for (int t = 0; t < ntiles; t++) {
        CPWAIT0();
        __syncthreads();             // single barrier per tile: protects both fill visibility
                                     // and buffer reuse (all warps are past compute(t-1) here)

        const uint32_t base = sm0 + (uint32_t)(t & 1) * BUFB;
        const uint32_t pAh = base + aoff, pAl = base + ASUB + aoff;
        const uint32_t pBh = base + 2 * ASUB + boff, pBl = base + 3 * ASUB + boff;

        // ---- ks = 0: load A frags first, then kick next tile's fills, then mma ----
        uint32_t ah[2][4], al[2][4];
        LDMX4(ah[0], pAh);
        LDMX4(ah[1], pAh + 16 * PADK * 2);
        LDMX4(al[0], pAl);
        LDMX4(al[1], pAl + 16 * PADK * 2);

        if (t + 1 < ntiles) fill(t + 1);   // issue slots overlap the mma stream below

        #pragma unroll
        for (int p = 0; p < 4; p++) {
            uint32_t bh[4], bl[4];
            LDMX4(bh, pBh + (uint32_t)(p * 16 * PADK * 2));
            LDMX4(bl, pBl + (uint32_t)(p * 16 * PADK * 2));
            #pragma unroll
            for (int q = 0; q < 2; q++) {
                const int nt = 2 * p + q;
                uint32_t bqh[2] = { bh[2 * q], bh[2 * q + 1] };
                uint32_t bql[2] = { bl[2 * q], bl[2 * q + 1] };
                mma16816(acc[0][nt], ah[0], bqh);
                mma16816(acc[0][nt], ah[0], bql);
                mma16816(acc[0][nt], al[0], bqh);
                mma16816(acc[1][nt], ah[1], bqh);
                mma16816(acc[1][nt], ah[1], bql);
                mma16816(acc[1][nt], al[1], bqh);
            }
        }

        // ---- ks = 1 ----
        LDMX4(ah[0], pAh + 32);
        LDMX4(ah[1], pAh + 32 + 16 * PADK * 2);
        LDMX4(al[0], pAl + 32);
        LDMX4(al[1], pAl + 32 + 16 * PADK * 2);
        #pragma unroll
        for (int p = 0; p < 4; p++) {
            uint32_t bh[4], bl[4];
            LDMX4(bh, pBh + 32 + (uint32_t)(p * 16 * PADK * 2));
            LDMX4(bl, pBl + 32 + (uint32_t)(p * 16 * PADK * 2));
            #pragma unroll
            for (int q = 0; q < 2; q++) {
                const int nt = 2 * p + q;
                uint32_t bqh[2] = { bh[2 * q], bh[2 * q + 1] };
                uint32_t bql[2] = { bl[2 * q], bl[2 * q + 1] };
                mma16816(acc[0][nt], ah[0], bqh);
                mma16816(acc[0][nt], ah[0], bql);
                mma16816(acc[0][nt], al[0], bqh);
                mma16816(acc[1][nt], ah[1], bqh);
                mma16816(acc[1][nt], ah[1], bql);
                mma16816(acc[1][nt], al[1], bqh);
            }
        }
    }

    // ---- store C ----
    const int g   = lane >> 2;
    const int tig = lane & 3;
    #pragma unroll
    for (int mt = 0; mt < 2; mt++) {
        #pragma unroll
        for (int nt = 0; nt < 8; nt++) {
            int r = row0 + wm * 32 + mt * 16 + g;
            int c = n0g + wn * 64 + nt * 8 + 2 * tig;
            if (r < M)
                *reinterpret_cast<float2*>(&g_y[(size_t)r * 256 + c]) =
                    make_float2(acc[mt][nt][0], acc[mt][nt][1]);
            if (r + 8 < M)
                *reinterpret_cast<float2*>(&g_y[(size_t)(r + 8) * 256 + c]) =
                    make_float2(acc[mt][nt][2], acc[mt][nt][3]);
        }
    }
}

// ---------------- gather (bucketed) + combine ----------------
__global__ void gather_combine(const float* __restrict__ bias) {
    int warp = (blockIdx.x * blockDim.x + threadIdx.x) >> 5;
    int lane = threadIdx.x & 31;
    if (warp >= NN) return;
    int e0 = g_start[warp];
    int deg = g_deg[warp];
    int e1 = e0 + deg;
    float4 a0 = make_float4(0.f, 0.f, 0.f, 0.f);
    float4 a1 = make_float4(0.f, 0.f, 0.f, 0.f);
    float4 a2 = make_float4(0.f, 0.f, 0.f, 0.f);
    float4 a3 = make_float4(0.f, 0.f, 0.f, 0.f);
    int e = e0;
    for (; e + 4 <= e1; e += 4) {
        int s0 = g_csr[e], s1 = g_csr[e + 1], s2 = g_csr[e + 2], s3 = g_csr[e + 3];
        float4 v0 = reinterpret_cast<const float4*>(g_y + (size_t)s0 * 256)[lane];
        float4 v1 = reinterpret_cast<const float4*>(g_y + (size_t)s1 * 256)[lane];
        float4 v2 = reinterpret_cast<const float4*>(g_y + (size_t)s2 * 256)[lane];
        float4 v3 = reinterpret_cast<const float4*>(g_y + (size_t)s3 * 256)[lane];
        a0.x += v0.x; a0.y += v0.y; a0.z += v0.z; a0.w += v0.w;
        a1.x += v1.x; a1.y += v1.y; a1.z += v1.z; a1.w += v1.w;
        a2.x += v2.x; a2.y += v2.y; a2.z += v2.z; a2.w += v2.w;
        a3.x += v3.x; a3.y += v3.y; a3.z += v3.z; a3.w += v3.w;
    }
    for (; e < e1; e++) {
        int s = g_csr[e];
        float4 v = reinterpret_cast<const float4*>(g_y + (size_t)s * 256)[lane];
        a0.x += v.x; a0.y += v.y; a0.z += v.z; a0.w += v.w;
    }
    float4 acc;
    acc.x = (a0.x + a1.x) + (a2.x + a3.x);
    acc.y = (a0.y + a1.y) + (a2.y + a3.y);
    acc.z = (a0.z + a1.z) + (a2.z + a3.z);
    acc.w = (a0.w + a1.w) + (a2.w + a3.w);
    float invd = 1.f / fmaxf((float)deg, 1.f);
    float4 r  = reinterpret_cast<const float4*>(g_y + (size_t)warp * 256 + 128)[lane];
    float4 b4 = reinterpret_cast<const float4*>(bias)[lane];
    float4 o;
    o.x = acc.x * invd + r.x + b4.x;
    o.y = acc.y * invd + r.y + b4.y;
    o.z = acc.z * invd + r.z + b4.z;
    o.w = acc.w * invd + r.w + b4.w;
    reinterpret_cast<float4*>(g_hpre + (size_t)warp * HID)[lane] = o;
}

// ---------------- BatchNorm ----------------
__global__ void bn_stats_k() {       // 256 blocks, no atomics / no zeroing
    int f = threadIdx.x;             // 128
    float s = 0.f, s2 = 0.f;
    for (int r = blockIdx.x; r < NN; r += 256) {
        float v = g_hpre[(size_t)r * HID + f];
        s += v; s2 += v * v;
    }
    g_part[blockIdx.x * 256 + f]       = s;
    g_part[blockIdx.x * 256 + 128 + f] = s2;
}

// mode 0: relu + write bf16 hi/lo (feeds next GEMM); mode 1: plain + write fp32 g_h (feeds pool)
__global__ void bn_norm_k(const float* __restrict__ gamma, const float* __restrict__ beta,
                          int mode) {
    int f = threadIdx.x;
    float s = 0.f, s2 = 0.f;
    #pragma unroll 4
    for (int b = 0; b < 256; b++) {
        s  += g_part[b * 256 + f];
        s2 += g_part[b * 256 + 128 + f];
    }
    float mean = s * (1.f / NN);
    float var  = s2 * (1.f / NN) - mean * mean;
    float rstd = rsqrtf(var + BN_EPS);
    float g = gamma[f] * rstd;
    float b = beta[f] - mean * g;
    for (int r = blockIdx.x; r < NN; r += gridDim.x) {
        float v = g_hpre[(size_t)r * HID + f] * g + b;
        if (mode == 0) {
            v = fmaxf(v, 0.f);
            __nv_bfloat16 hi, lo;
            split_bf16(v, hi, lo);
            g_ahi[(size_t)r * HID + f] = hi;
            g_alo[(size_t)r * HID + f] = lo;
        } else {
            g_h[(size_t)r * HID + f] = v;
        }
    }
}

// ---------------- global max pool (batch is sorted) ----------------
__global__ void pool_init_k() {
    g_pool[blockIdx.x * HID + threadIdx.x] = 0x007fffffu;  // fenc(-inf)
}

#define POOL_CHUNK 512
__global__ void pool_max_k(const int* __restrict__ batch) {
    int f = threadIdx.x;  // 128
    int r0 = blockIdx.x * POOL_CHUNK;
    int r1 = min(r0 + POOL_CHUNK, NN);
    int cur = -1;
    float m = -3.4e38f;
    for (int r = r0; r < r1; r++) {
        int gi = batch[r];
        if (gi != cur) {
            if (cur >= 0) atomicMax(&g_pool[cur * HID + f], fenc(m));
            cur = gi;
            m = -3.4e38f;
        }
        m = fmaxf(m, g_h[(size_t)r * HID + f]);
    }
    if (cur >= 0) atomicMax(&g_pool[cur * HID + f], fenc(m));
}

// ---------------- final linear ----------------
__global__ void final_linear_k(const float* __restrict__ Wlin, const float* __restrict__ blin,
                               float* __restrict__ out) {
    __shared__ float sh[HID];
    int g = blockIdx.x, t = threadIdx.x;
    sh[t] = fdec(g_pool[g * HID + t]);
    __syncthreads();
    if (t < NCLS) {
        float a = blin[t];
        #pragma unroll 8
        for (int k = 0; k < HID; k++) a += sh[k] * Wlin[t * HID + k];
        out[g * NCLS + t] = a;
    }
}

// ---------------- launch ----------------
extern "C" void kernel_launch(void* const* d_in, const int* in_sizes, int n_in,
                              void* d_out, int out_size) {
    const float* x    = (const float*)d_in[0];
    const int*   src  = (const int*)d_in[1];
    const int*   dst  = src + NE;
    const int*   batch = (const int*)d_in[2];
    const float* W1l = (const float*)d_in[3];
    const float* b1  = (const float*)d_in[4];
    const float* W1r = (const float*)d_in[5];
    const float* g1  = (const float*)d_in[6];
    const float* be1 = (const float*)d_in[7];
    const float* W2l = (const float*)d_in[8];
    const float* b2  = (const float*)d_in[9];
    const float* W2r = (const float*)d_in[10];
    const float* g2  = (const float*)d_in[11];
    const float* be2 = (const float*)d_in[12];
    const float* W3l = (const float*)d_in[13];
    const float* b3  = (const float*)d_in[14];
    const float* W3r = (const float*)d_in[15];
    const float* g3  = (const float*)d_in[16];
    const float* be3 = (const float*)d_in[17];
    const float* Wlin = (const float*)d_in[18];
    const float* blin = (const float*)d_in[19];
    float* out = (float*)d_out;

    cudaFuncSetAttribute(gemm_mma, cudaFuncAttributeMaxDynamicSharedMemorySize, GEMM_SMEM);

    const int mblocks = (NN + 127) / 128;          // 391
    const int gblocks = mblocks * 2;               // paired 1D grid
    const int gwarps  = (NN * 32 + 255) / 256;

    // ----- prologue + layer-1 GEMM first (ncu's fixed capture slot lands on the GEMM) -----
    convert_w_k<<<(256 * IN_DIM + 255) / 256, 256>>>(W1l, W1r, IN_DIM);      // launch 1
    conv_x_k<<<(NN * IN_DIM / 4 + 255) / 256, 256>>>(x);                     // launch 2
    zero_deg_k<<<(NN + 255) / 256, 256>>>();                                 // launch 3
    gemm_mma<<<gblocks, 256, GEMM_SMEM>>>(NN, IN_DIM);                       // launch 4 (profiled)

    // CSR build (independent of GEMM)
    hist_k<<<(NE + 255) / 256, 256>>>(dst);
    alloc_off_k<<<(NN + 255) / 256, 256>>>();
    fill_k<<<(NE + 255) / 256, 256>>>(src, dst);

    // ----- layer 1 tail -----
    gather_combine<<<gwarps, 256>>>(b1);
    bn_stats_k<<<256, 128>>>();
    bn_norm_k<<<512, 128>>>(g1, be1, 0);

    // ----- layer 2 (K = 128) -----
    convert_w_k<<<(256 * HID + 255) / 256, 256>>>(W2l, W2r, HID);
    gemm_mma<<<gblocks, 256, GEMM_SMEM>>>(NN, HID);
    gather_combine<<<gwarps, 256>>>(b2);
    bn_stats_k<<<256, 128>>>();
    bn_norm_k<<<512, 128>>>(g2, be2, 0);

    // ----- layer 3 (K = 128, no relu, fp32 out) -----
    convert_w_k<<<(256 * HID + 255) / 256, 256>>>(W3l, W3r, HID);
    gemm_mma<<<gblocks, 256, GEMM_SMEM>>>(NN, HID);
    gather_combine<<<gwarps, 256>>>(b3);
    bn_stats_k<<<256, 128>>>();
    bn_norm_k<<<512, 128>>>(g3, be3, 1);

    // ----- pool + head -----
    pool_init_k<<<NG, HID>>>();
    pool_max_k<<<(NN + POOL_CHUNK - 1) / POOL_CHUNK, 128>>>(batch);
    final_linear_k<<<NG, HID>>>(Wlin, blin, out);
}

// round 7
// speedup vs baseline: 1.0162x; 1.0106x over previous
#include <cuda_runtime.h>
#include <cuda_bf16.h>
#include <cstdint>

#define NN      50000
#define NE      400000
#define NG      128
#define IN_DIM  768
#define HID     128
#define NCLS    11
#define BN_EPS  1e-5f

// ---------------- scratch (device globals; no allocation allowed) ----------------
__device__ float    g_y[(size_t)NN * 256];      // [NN,256]: cols 0..127 = agg-side, 128..255 = self-side
__device__ float    g_hpre[(size_t)NN * HID];   // pre-BN activations
__device__ float    g_h[(size_t)NN * HID];      // post-BN layer-3 activations (fp32, for pool)
__device__ __align__(16) __nv_bfloat16 g_ahi[(size_t)NN * IN_DIM];  // activation hi (K=768 or 128)
__device__ __align__(16) __nv_bfloat16 g_alo[(size_t)NN * IN_DIM];  // activation lo
__device__ __align__(16) __nv_bfloat16 g_whi[256 * IN_DIM];         // fused [Wl;Wr] hi
__device__ __align__(16) __nv_bfloat16 g_wlo[256 * IN_DIM];         // fused [Wl;Wr] lo
__device__ int      g_deg[NN];
__device__ int      g_start[NN];
__device__ int      g_cursor[NN];
__device__ int      g_total;
__device__ int      g_csr[NE];                  // src ids bucketed by dst (unordered buckets)
__device__ float    g_part[256 * 256];          // bn partials
__device__ float    g_coef[256];                // [0:128)=scale g, [128:256)=shift b
__device__ unsigned g_pool[NG * HID];           // order-preserving-encoded max

// ---------------- helpers ----------------
__device__ __forceinline__ uint32_t smem_u32(const void* p) {
    uint32_t a;
    asm("{ .reg .u64 t; cvta.to.shared.u64 t, %1; cvt.u32.u64 %0, t; }" : "=r"(a) : "l"(p));
    return a;
}
__device__ __forceinline__ unsigned fenc(float f) {
    unsigned u = __float_as_uint(f);
    return (u >> 31) ? ~u : (u | 0x80000000u);
}
__device__ __forceinline__ float fdec(unsigned e) {
    return (e >> 31) ? __uint_as_float(e & 0x7fffffffu) : __uint_as_float(~e);
}

#define LDMX4(d, a)                                                                  \
    asm volatile("ldmatrix.sync.aligned.m8n8.x4.shared.b16 {%0,%1,%2,%3}, [%4];"     \
        : "=r"((d)[0]), "=r"((d)[1]), "=r"((d)[2]), "=r"((d)[3]) : "r"(a))

#define CPASYNC16(dst, src) \
    asm volatile("cp.async.cg.shared.global [%0], [%1], 16;" :: "r"(dst), "l"(src) : "memory")
#define CPASYNC16Z(dst, src, sz) \
    asm volatile("cp.async.cg.shared.global [%0], [%1], 16, %2;" :: "r"(dst), "l"(src), "r"(sz) : "memory")
#define CPCOMMIT() asm volatile("cp.async.commit_group;" ::: "memory")
#define CPWAIT0()  asm volatile("cp.async.wait_group 0;" ::: "memory")

__device__ __forceinline__ void mma16816(float* c, const uint32_t* a, const uint32_t* b) {
    asm volatile(
        "mma.sync.aligned.m16n8k16.row.col.f32.bf16.bf16.f32 "
        "{%0,%1,%2,%3}, {%4,%5,%6,%7}, {%8,%9}, {%0,%1,%2,%3};"
        : "+f"(c[0]), "+f"(c[1]), "+f"(c[2]), "+f"(c[3])
        : "r"(a[0]), "r"(a[1]), "r"(a[2]), "r"(a[3]), "r"(b[0]), "r"(b[1]));
}

__device__ __forceinline__ void split_bf16(float v, __nv_bfloat16& hi, __nv_bfloat16& lo) {
    hi = __float2bfloat16(v);
    lo = __float2bfloat16(v - __bfloat162float(hi));
}

// ---------------- CSR build ----------------
__global__ void zero_deg_k() {
    int i = blockIdx.x * blockDim.x + threadIdx.x;
    if (i < NN) g_deg[i] = 0;
    if (i == 0) g_total = 0;
}

__global__ void hist_k(const int* __restrict__ dst) {
    int e = blockIdx.x * blockDim.x + threadIdx.x;
    if (e < NE) atomicAdd(&g_deg[dst[e]], 1);
}

__global__ void alloc_off_k() {
    int i = blockIdx.x * blockDim.x + threadIdx.x;
    int lane = threadIdx.x & 31;
    int d = (i < NN) ? g_deg[i] : 0;
    int inc = d;
    #pragma unroll
    for (int s = 1; s < 32; s <<= 1) {
        int v = __shfl_up_sync(0xffffffffu, inc, s);
        if (lane >= s) inc += v;
    }
    int ex  = inc - d;
    int tot = __shfl_sync(0xffffffffu, inc, 31);
    int base = 0;
    if (lane == 31) base = atomicAdd(&g_total, tot);
    base = __shfl_sync(0xffffffffu, base, 31);
    if (i < NN) { g_start[i] = base + ex; g_cursor[i] = base + ex; }
}

__global__ void fill_k(const int* __restrict__ src, const int* __restrict__ dst) {
    int e = blockIdx.x * blockDim.x + threadIdx.x;
    if (e < NE) {
        int p = atomicAdd(&g_cursor[dst[e]], 1);
        g_csr[p] = src[e];
    }
}

// ---------------- conversions ----------------
__global__ void convert_w_k(const float* __restrict__ Wl, const float* __restrict__ Wr, int K) {
    int idx = blockIdx.x * blockDim.x + threadIdx.x;
    if (idx >= 256 * K) return;
    int row = idx / K, col = idx - row * K;
    float v = (row < 128) ? Wl[row * K + col] : Wr[(row - 128) * K + col];
    __nv_bfloat16 hi, lo;
    split_bf16(v, hi, lo);
    g_whi[idx] = hi;
    g_wlo[idx] = lo;
}

__global__ void conv_x_k(const float* __restrict__ x) {
    size_t i = (size_t)(blockIdx.x * blockDim.x + threadIdx.x) * 4;
    if (i >= (size_t)NN * IN_DIM) return;
    float4 v = *reinterpret_cast<const float4*>(x + i);
    __nv_bfloat16 h0, h1, h2, h3, l0, l1, l2, l3;
    split_bf16(v.x, h0, l0); split_bf16(v.y, h1, l1);
    split_bf16(v.z, h2, l2); split_bf16(v.w, h3, l3);
    __nv_bfloat162 hp0 = __halves2bfloat162(h0, h1), hp1 = __halves2bfloat162(h2, h3);
    __nv_bfloat162 lp0 = __halves2bfloat162(l0, l1), lp1 = __halves2bfloat162(l2, l3);
    *reinterpret_cast<uint2*>(g_ahi + i) = make_uint2(*(uint32_t*)&hp0, *(uint32_t*)&hp1);
    *reinterpret_cast<uint2*>(g_alo + i) = make_uint2(*(uint32_t*)&lp0, *(uint32_t*)&lp1);
}

// ---------------- tensor-core GEMM ----------------
// Y[M,256] = A[M,K] @ W[256,K]^T as Ahi@Whi + Ahi@Wlo + Alo@Whi.
// 1D grid, paired blocks share A tiles via L2. BM=128, BN=128, BK=32.
// 8 warps (4M x 2N), warp tile 32x64. mma issue is term-major so every
// accumulator RAW reuse is 4 instructions apart (covers HMMA latency).
#define PADK  40
#define ASUB  10240
#define BUFB  40960
#define GEMM_SMEM (2 * BUFB)

// one compute pass over a half-tile (ks offset in bytes: 0 or 32)
#define HALF_TILE(KOFF)                                                              \
    do {                                                                             \
        uint32_t ah[2][4], al[2][4];                                                 \
        LDMX4(ah[0], pAh + (KOFF));                                                  \
        LDMX4(ah[1], pAh + (KOFF) + 16 * PADK * 2);                                  \
        LDMX4(al[0], pAl + (KOFF));                                                  \
        LDMX4(al[1], pAl + (KOFF) + 16 * PADK * 2);                                  \
        _Pragma("unroll")                                                            \
        for (int p = 0; p < 4; p++) {                                                \
            uint32_t bh[4], bl[4];                                                   \
            LDMX4(bh, pBh + (KOFF) + (uint32_t)(p * 16 * PADK * 2));                 \
            LDMX4(bl, pBl + (KOFF) + (uint32_t)(p * 16 * PADK * 2));                 \
            const int n0 = 2 * p, n1 = 2 * p + 1;                                    \
            /* hh pass: 4 independent accs */                                        \
            mma16816(acc[0][n0], ah[0], bh);                                         \
            mma16816(acc[1][n0], ah[1], bh);                                         \
            mma16816(acc[0][n1], ah[0], bh + 2);                                     \
            mma16816(acc[1][n1], ah[1], bh + 2);                                     \
            /* hl pass */                                                            \
            mma16816(acc[0][n0], ah[0], bl);                                         \
            mma16816(acc[1][n0], ah[1], bl);                                         \
            mma16816(acc[0][n1], ah[0], bl + 2);                                     \
            mma16816(acc[1][n1], ah[1], bl + 2);                                     \
            /* lh pass */                                                            \
            mma16816(acc[0][n0], al[0], bh);                                         \
            mma16816(acc[1][n0], al[1], bh);                                         \
            mma16816(acc[0][n1], al[0], bh + 2);                                     \
            mma16816(acc[1][n1], al[1], bh + 2);                                     \
        }                                                                            \
    } while (0)

__global__ __launch_bounds__(256, 2)
void gemm_mma(int M, int K) {
    extern __shared__ char dsm[];
    const uint32_t sm0 = smem_u32(dsm);

    const int tid  = threadIdx.x;
    const int lane = tid & 31;
    const int wid  = tid >> 5;
    const int wm   = wid & 3;
    const int wn   = wid >> 2;
    const int row0 = (blockIdx.x >> 1) * 128;
    const int n0g  = (blockIdx.x & 1) * 128;

    const int a_row = lane & 15;
    const int a_kh  = (lane >> 4) * 8;
    const uint32_t aoff = (uint32_t)(((wm * 32 + a_row) * PADK + a_kh) * 2);
    const int b_row = ((lane >> 4) << 3) + (lane & 7);
    const int b_kh  = ((lane >> 3) & 1) * 8;
    const uint32_t boff = (uint32_t)(((wn * 64 + b_row) * PADK + b_kh) * 2);

    float acc[2][8][4];
    #pragma unroll
    for (int i = 0; i < 2; i++)
        #pragma unroll
        for (int j = 0; j < 8; j++)
            #pragma unroll
            for (int q = 0; q < 4; q++) acc[i][j][q] = 0.f;

    const int ntiles = K / 32;

    auto fill = [&](int t) {
        const int k0 = t * 32;
        const uint32_t base = sm0 + (uint32_t)(t & 1) * BUFB;
        #pragma unroll
        for (int i = 0; i < 2; i++) {
            int s   = tid + 256 * i;
            int r   = s >> 2;
            int seg = s & 3;
            uint32_t off = (uint32_t)(r * (PADK * 2) + seg * 16);
            size_t go = (size_t)(row0 + r) * K + k0 + seg * 8;
            int sz = (row0 + r < M) ? 16 : 0;
            CPASYNC16Z(base + off,        (const void*)(g_ahi + go), sz);
            CPASYNC16Z(base + ASUB + off, (const void*)(g_alo + go), sz);
        }
        #pragma unroll
        for (int i = 0; i < 2; i++) {
            int s   = tid + 256 * i;
            int r   = s >> 2;
            int seg = s & 3;
            uint32_t off = (uint32_t)(r * (PADK * 2) + seg * 16);
            size_t go = (size_t)(n0g + r) * K + k0 + seg * 8;
            CPASYNC16(base + 2 * ASUB + off, (const void*)(g_whi + go));
            CPASYNC16(base + 3 * ASUB + off, (const void*)(g_wlo + go));
        }
        CPCOMMIT();
    };

    fill(0);
    for (int t = 0; t < ntiles; t++) {
        CPWAIT0();
        __syncthreads();

        const uint32_t base = sm0 + (uint32_t)(t & 1) * BUFB;
        const uint32_t pAh = base + aoff, pAl = base + ASUB + aoff;
        const uint32_t pBh = base + 2 * ASUB + boff, pBl = base + 3 * ASUB + boff;

        if (t + 1 < ntiles) fill(t + 1);

        HALF_TILE(0u);
        HALF_TILE(32u);
    }

    // ---- store C ----
    const int g   = lane >> 2;
    const int tig = lane & 3;
    #pragma unroll
    for (int mt = 0; mt < 2; mt++) {
        #pragma unroll
        for (int nt = 0; nt < 8; nt++) {
            int r = row0 + wm * 32 + mt * 16 + g;
            int c = n0g + wn * 64 + nt * 8 + 2 * tig;
            if (r < M)
                *reinterpret_cast<float2*>(&g_y[(size_t)r * 256 + c]) =
                    make_float2(acc[mt][nt][0], acc[mt][nt][1]);
            if (r + 8 < M)
                *reinterpret_cast<float2*>(&g_y[(size_t)(r + 8) * 256 + c]) =
                    make_float2(acc[mt][nt][2], acc[mt][nt][3]);
        }
    }
}

// ---------------- gather (bucketed) + combine ----------------
__global__ void gather_combine(const float* __restrict__ bias) {
    int warp = (blockIdx.x * blockDim.x + threadIdx.x) >> 5;
    int lane = threadIdx.x & 31;
    if (warp >= NN) return;
    int e0 = g_start[warp];
    int deg = g_deg[warp];
    int e1 = e0 + deg;
    float4 a0 = make_float4(0.f, 0.f, 0.f, 0.f);
    float4 a1 = make_float4(0.f, 0.f, 0.f, 0.f);
    float4 a2 = make_float4(0.f, 0.f, 0.f, 0.f);
    float4 a3 = make_float4(0.f, 0.f, 0.f, 0.f);
    int e = e0;
    for (; e + 4 <= e1; e += 4) {
        int s0 = g_csr[e], s1 = g_csr[e + 1], s2 = g_csr[e + 2], s3 = g_csr[e + 3];
        float4 v0 = reinterpret_cast<const float4*>(g_y + (size_t)s0 * 256)[lane];
        float4 v1 = reinterpret_cast<const float4*>(g_y + (size_t)s1 * 256)[lane];
        float4 v2 = reinterpret_cast<const float4*>(g_y + (size_t)s2 * 256)[lane];
        float4 v3 = reinterpret_cast<const float4*>(g_y + (size_t)s3 * 256)[lane];
        a0.x += v0.x; a0.y += v0.y; a0.z += v0.z; a0.w += v0.w;
        a1.x += v1.x; a1.y += v1.y; a1.z += v1.z; a1.w += v1.w;
        a2.x += v2.x; a2.y += v2.y; a2.z += v2.z; a2.w += v2.w;
        a3.x += v3.x; a3.y += v3.y; a3.z += v3.z; a3.w += v3.w;
    }
    for (; e < e1; e++) {
        int s = g_csr[e];
        float4 v = reinterpret_cast<const float4*>(g_y + (size_t)s * 256)[lane];
        a0.x += v.x; a0.y += v.y; a0.z += v.z; a0.w += v.w;
    }
    float4 acc;
    acc.x = (a0.x + a1.x) + (a2.x + a3.x);
    acc.y = (a0.y + a1.y) + (a2.y + a3.y);
    acc.z = (a0.z + a1.z) + (a2.z + a3.z);
    acc.w = (a0.w + a1.w) + (a2.w + a3.w);
    float invd = 1.f / fmaxf((float)deg, 1.f);
    float4 r  = reinterpret_cast<const float4*>(g_y + (size_t)warp * 256 + 128)[lane];
    float4 b4 = reinterpret_cast<const float4*>(bias)[lane];
    float4 o;
    o.x = acc.x * invd + r.x + b4.x;
    o.y = acc.y * invd + r.y + b4.y;
    o.z = acc.z * invd + r.z + b4.z;
    o.w = acc.w * invd + r.w + b4.w;
    reinterpret_cast<float4*>(g_hpre + (size_t)warp * HID)[lane] = o;
}

// ---------------- BatchNorm ----------------
__global__ void bn_stats_k() {       // 256 blocks, no atomics / no zeroing
    int f = threadIdx.x;             // 128
    float s = 0.f, s2 = 0.f;
    for (int r = blockIdx.x; r < NN; r += 256) {
        float v = g_hpre[(size_t)r * HID + f];
        s += v; s2 += v * v;
    }
    g_part[blockIdx.x * 256 + f]       = s;
    g_part[blockIdx.x * 256 + 128 + f] = s2;
}

// single block: reduce partials -> per-feature scale/shift
__global__ void reduce_stats_k(const float* __restrict__ gamma, const float* __restrict__ beta) {
    int f = threadIdx.x;  // 128
    float s = 0.f, s2 = 0.f;
    #pragma unroll 4
    for (int b = 0; b < 256; b++) {
        s  += g_part[b * 256 + f];
        s2 += g_part[b * 256 + 128 + f];
    }
    float mean = s * (1.f / NN);
    float var  = s2 * (1.f / NN) - mean * mean;
    float rstd = rsqrtf(var + BN_EPS);
    float g = gamma[f] * rstd;
    g_coef[f]       = g;
    g_coef[f + 128] = beta[f] - mean * g;
}

// mode 0: relu + write bf16 hi/lo; mode 1: plain + write fp32 g_h
__global__ void bn_norm_k(int mode) {
    int f = threadIdx.x;
    float g = g_coef[f];
    float b = g_coef[f + 128];
    for (int r = blockIdx.x; r < NN; r += gridDim.x) {
        float v = g_hpre[(size_t)r * HID + f] * g + b;
        if (mode == 0) {
            v = fmaxf(v, 0.f);
            __nv_bfloat16 hi, lo;
            split_bf16(v, hi, lo);
            g_ahi[(size_t)r * HID + f] = hi;
            g_alo[(size_t)r * HID + f] = lo;
        } else {
            g_h[(size_t)r * HID + f] = v;
        }
    }
}

// ---------------- global max pool (batch is sorted) ----------------
__global__ void pool_init_k() {
    g_pool[blockIdx.x * HID + threadIdx.x] = 0x007fffffu;  // fenc(-inf)
}

#define POOL_CHUNK 512
__global__ void pool_max_k(const int* __restrict__ batch) {
    int f = threadIdx.x;  // 128
    int r0 = blockIdx.x * POOL_CHUNK;
    int r1 = min(r0 + POOL_CHUNK, NN);
    int cur = -1;
    float m = -3.4e38f;
    for (int r = r0; r < r1; r++) {
        int gi = batch[r];
        if (gi != cur) {
            if (cur >= 0) atomicMax(&g_pool[cur * HID + f], fenc(m));
            cur = gi;
            m = -3.4e38f;
        }
        m = fmaxf(m, g_h[(size_t)r * HID + f]);
    }
    if (cur >= 0) atomicMax(&g_pool[cur * HID + f], fenc(m));
}

// ---------------- final linear ----------------
__global__ void final_linear_k(const float* __restrict__ Wlin, const float* __restrict__ blin,
                               float* __restrict__ out) {
    __shared__ float sh[HID];
    int g = blockIdx.x, t = threadIdx.x;
    sh[t] = fdec(g_pool[g * HID + t]);
    __syncthreads();
    if (t < NCLS) {
        float a = blin[t];
        #pragma unroll 8
        for (int k = 0; k < HID; k++) a += sh[k] * Wlin[t * HID + k];
        out[g * NCLS + t] = a;
    }
}

// ---------------- launch ----------------
extern "C" void kernel_launch(void* const* d_in, const int* in_sizes, int n_in,
                              void* d_out, int out_size) {
    const float* x    = (const float*)d_in[0];
    const int*   src  = (const int*)d_in[1];
    const int*   dst  = src + NE;
    const int*   batch = (const int*)d_in[2];
    const float* W1l = (const float*)d_in[3];
    const float* b1  = (const float*)d_in[4];
    const float* W1r = (const float*)d_in[5];
    const float* g1  = (const float*)d_in[6];
    const float* be1 = (const float*)d_in[7];
    const float* W2l = (const float*)d_in[8];
    const float* b2  = (const float*)d_in[9];
    const float* W2r = (const float*)d_in[10];
    const float* g2  = (const float*)d_in[11];
    const float* be2 = (const float*)d_in[12];
    const float* W3l = (const float*)d_in[13];
    const float* b3  = (const float*)d_in[14];
    const float* W3r = (const float*)d_in[15];
    const float* g3  = (const float*)d_in[16];
    const float* be3 = (const float*)d_in[17];
    const float* Wlin = (const float*)d_in[18];
    const float* blin = (const float*)d_in[19];
    float* out = (float*)d_out;

    cudaFuncSetAttribute(gemm_mma, cudaFuncAttributeMaxDynamicSharedMemorySize, GEMM_SMEM);

    const int mblocks = (NN + 127) / 128;          // 391
    const int gblocks = mblocks * 2;
    const int gwarps  = (NN * 32 + 255) / 256;

    // ----- prologue + layer-1 GEMM (ncu capture slot = 4th launch) -----
    convert_w_k<<<(256 * IN_DIM + 255) / 256, 256>>>(W1l, W1r, IN_DIM);
    conv_x_k<<<(NN * IN_DIM / 4 + 255) / 256, 256>>>(x);
    zero_deg_k<<<(NN + 255) / 256, 256>>>();
    gemm_mma<<<gblocks, 256, GEMM_SMEM>>>(NN, IN_DIM);                       // profiled

    // CSR build
    hist_k<<<(NE + 255) / 256, 256>>>(dst);
    alloc_off_k<<<(NN + 255) / 256, 256>>>();
    fill_k<<<(NE + 255) / 256, 256>>>(src, dst);

    // ----- layer 1 tail -----
    gather_combine<<<gwarps, 256>>>(b1);
    bn_stats_k<<<256, 128>>>();
    reduce_stats_k<<<1, 128>>>(g1, be1);
    bn_norm_k<<<512, 128>>>(0);

    // ----- layer 2 -----
    convert_w_k<<<(256 * HID + 255) / 256, 256>>>(W2l, W2r, HID);
    gemm_mma<<<gblocks, 256, GEMM_SMEM>>>(NN, HID);
    gather_combine<<<gwarps, 256>>>(b2);
    bn_stats_k<<<256, 128>>>();
    reduce_stats_k<<<1, 128>>>(g2, be2);
    bn_norm_k<<<512, 128>>>(0);

    // ----- layer 3 -----
    convert_w_k<<<(256 * HID + 255) / 256, 256>>>(W3l, W3r, HID);
    gemm_mma<<<gblocks, 256, GEMM_SMEM>>>(NN, HID);
    gather_combine<<<gwarps, 256>>>(b3);
    bn_stats_k<<<256, 128>>>();
    reduce_stats_k<<<1, 128>>>(g3, be3);
    bn_norm_k<<<512, 128>>>(1);

    // ----- pool + head -----
    pool_init_k<<<NG, HID>>>();
    pool_max_k<<<(NN + POOL_CHUNK - 1) / POOL_CHUNK, 128>>>(batch);
    final_linear_k<<<NG, HID>>>(Wlin, blin, out);
}

// round 8
// speedup vs baseline: 1.1601x; 1.1416x over previous
#include <cuda_runtime.h>
#include <cuda_fp16.h>
#include <cstdint>

#define NN      50000
#define NE      400000
#define NG      128
#define IN_DIM  768
#define HID     128
#define NCLS    11
#define BN_EPS  1e-5f

// ---------------- scratch (device globals; no allocation allowed) ----------------
__device__ float    g_y[(size_t)NN * 256];      // [NN,256]: cols 0..127 = agg-side, 128..255 = self-side
__device__ float    g_hpre[(size_t)NN * HID];   // pre-BN activations
__device__ float    g_h[(size_t)NN * HID];      // post-BN layer-3 activations (fp32, for pool)
__device__ __align__(16) __half g_af16[(size_t)NN * IN_DIM];  // activations, single fp16
__device__ __align__(16) __half g_wh[256 * IN_DIM];           // fused [Wl;Wr] fp16 hi
__device__ __align__(16) __half g_wl[256 * IN_DIM];           // fused [Wl;Wr] fp16 lo (residual)
__device__ int      g_deg[NN];
__device__ int      g_start[NN];
__device__ int      g_cursor[NN];
__device__ int      g_total;
__device__ int      g_csr[NE];                  // src ids bucketed by dst (unordered buckets)
__device__ float    g_part[256 * 256];          // bn partials
__device__ float    g_coef[256];                // [0:128)=scale, [128:256)=shift
__device__ unsigned g_pool[NG * HID];           // order-preserving-encoded max

// ---------------- helpers ----------------
__device__ __forceinline__ uint32_t smem_u32(const void* p) {
    uint32_t a;
    asm("{ .reg .u64 t; cvta.to.shared.u64 t, %1; cvt.u32.u64 %0, t; }" : "=r"(a) : "l"(p));
    return a;
}
__device__ __forceinline__ unsigned fenc(float f) {
    unsigned u = __float_as_uint(f);
    return (u >> 31) ? ~u : (u | 0x80000000u);
}
__device__ __forceinline__ float fdec(unsigned e) {
    return (e >> 31) ? __uint_as_float(e & 0x7fffffffu) : __uint_as_float(~e);
}

#define LDMX4(d, a)                                                                  \
    asm volatile("ldmatrix.sync.aligned.m8n8.x4.shared.b16 {%0,%1,%2,%3}, [%4];"     \
        : "=r"((d)[0]), "=r"((d)[1]), "=r"((d)[2]), "=r"((d)[3]) : "r"(a))

#define CPASYNC16(dst, src) \
    asm volatile("cp.async.cg.shared.global [%0], [%1], 16;" :: "r"(dst), "l"(src) : "memory")
#define CPASYNC16Z(dst, src, sz) \
    asm volatile("cp.async.cg.shared.global [%0], [%1], 16, %2;" :: "r"(dst), "l"(src), "r"(sz) : "memory")
#define CPCOMMIT() asm volatile("cp.async.commit_group;" ::: "memory")
#define CPWAIT0()  asm volatile("cp.async.wait_group 0;" ::: "memory")

__device__ __forceinline__ void mma16816(float* c, const uint32_t* a, const uint32_t* b) {
    asm volatile(
        "mma.sync.aligned.m16n8k16.row.col.f32.f16.f16.f32 "
        "{%0,%1,%2,%3}, {%4,%5,%6,%7}, {%8,%9}, {%0,%1,%2,%3};"
        : "+f"(c[0]), "+f"(c[1]), "+f"(c[2]), "+f"(c[3])
        : "r"(a[0]), "r"(a[1]), "r"(a[2]), "r"(a[3]), "r"(b[0]), "r"(b[1]));
}

// ---------------- CSR build ----------------
__global__ void zero_deg_k() {          // also initializes the pool maxima (independent of data)
    int i = blockIdx.x * blockDim.x + threadIdx.x;
    if (i < NN) g_deg[i] = 0;
    if (i < NG * HID) g_pool[i] = 0x007fffffu;   // fenc(-inf)
    if (i == 0) g_total = 0;
}

__global__ void hist_k(const int* __restrict__ dst) {
    int e = blockIdx.x * blockDim.x + threadIdx.x;
    if (e < NE) atomicAdd(&g_deg[dst[e]], 1);
}

__global__ void alloc_off_k() {
    int i = blockIdx.x * blockDim.x + threadIdx.x;
    int lane = threadIdx.x & 31;
    int d = (i < NN) ? g_deg[i] : 0;
    int inc = d;
    #pragma unroll
    for (int s = 1; s < 32; s <<= 1) {
        int v = __shfl_up_sync(0xffffffffu, inc, s);
        if (lane >= s) inc += v;
    }
    int ex  = inc - d;
    int tot = __shfl_sync(0xffffffffu, inc, 31);
    int base = 0;
    if (lane == 31) base = atomicAdd(&g_total, tot);
    base = __shfl_sync(0xffffffffu, base, 31);
    if (i < NN) { g_start[i] = base + ex; g_cursor[i] = base + ex; }
}

__global__ void fill_k(const int* __restrict__ src, const int* __restrict__ dst) {
    int e = blockIdx.x * blockDim.x + threadIdx.x;
    if (e < NE) {
        int p = atomicAdd(&g_cursor[dst[e]], 1);
        g_csr[p] = src[e];
    }
}

// ---------------- conversions ----------------
// weights: fused [Wl;Wr] -> fp16 hi + fp16 residual (W represented to ~22 bits)
__global__ void convert_w_k(const float* __restrict__ Wl, const float* __restrict__ Wr, int K) {
    int idx = blockIdx.x * blockDim.x + threadIdx.x;
    if (idx >= 256 * K) return;
    int row = idx / K, col = idx - row * K;
    float v = (row < 128) ? Wl[row * K + col] : Wr[(row - 128) * K + col];
    __half hi = __float2half(v);
    __half lo = __float2half(v - __half2float(hi));
    g_wh[idx] = hi;
    g_wl[idx] = lo;
}

// x (fp32 [NN,768]) -> single fp16
__global__ void conv_x_k(const float* __restrict__ x) {
    size_t i = (size_t)(blockIdx.x * blockDim.x + threadIdx.x) * 4;
    if (i >= (size_t)NN * IN_DIM) return;
    float4 v = *reinterpret_cast<const float4*>(x + i);
    __half2 p0 = __floats2half2_rn(v.x, v.y);
    __half2 p1 = __floats2half2_rn(v.z, v.w);
    *reinterpret_cast<uint2*>(g_af16 + i) =
        make_uint2(*(uint32_t*)&p0, *(uint32_t*)&p1);
}

// ---------------- tensor-core GEMM (fp16 2-term: A*Wh + A*Wl) ----------------
// Y[M,256] = A[M,K] @ W[256,K]^T, W exact via hi+lo fp16, A single fp16.
// 1D grid, paired blocks share A tiles via L2. BM=128, BN=128, BK=32.
// 8 warps (4M x 2N), warp tile 32x64; RAW reuse distance 4 on accumulators.
#define PADK  40
#define ASUB  10240                 // 128 rows * 80 B
#define BUFB  (3 * ASUB)            // A, Wh, Wl
#define GEMM_SMEM (2 * BUFB)

#define HALF_TILE(KOFF)                                                              \
    do {                                                                             \
        uint32_t ah[2][4];                                                           \
        LDMX4(ah[0], pA + (KOFF));                                                   \
        LDMX4(ah[1], pA + (KOFF) + 16 * PADK * 2);                                   \
        _Pragma("unroll")                                                            \
        for (int p = 0; p < 4; p++) {                                                \
            uint32_t bh[4], bl[4];                                                   \
            LDMX4(bh, pWh + (KOFF) + (uint32_t)(p * 16 * PADK * 2));                 \
            LDMX4(bl, pWl + (KOFF) + (uint32_t)(p * 16 * PADK * 2));                 \
            const int n0 = 2 * p, n1 = 2 * p + 1;                                    \
            mma16816(acc[0][n0], ah[0], bh);                                         \
            mma16816(acc[1][n0], ah[1], bh);                                         \
            mma16816(acc[0][n1], ah[0], bh + 2);                                     \
            mma16816(acc[1][n1], ah[1], bh + 2);                                     \
            mma16816(acc[0][n0], ah[0], bl);                                         \
            mma16816(acc[1][n0], ah[1], bl);                                         \
            mma16816(acc[0][n1], ah[0], bl + 2);                                     \
            mma16816(acc[1][n1], ah[1], bl + 2);                                     \
        }                                                                            \
    } while (0)

__global__ __launch_bounds__(256, 2)
void gemm_mma(int M, int K) {
    extern __shared__ char dsm[];
    const uint32_t sm0 = smem_u32(dsm);

    const int tid  = threadIdx.x;
    const int lane = tid & 31;
    const int wid  = tid >> 5;
    const int wm   = wid & 3;
    const int wn   = wid >> 2;
    const int row0 = (blockIdx.x >> 1) * 128;
    const int n0g  = (blockIdx.x & 1) * 128;

    const int a_row = lane & 15;
    const int a_kh  = (lane >> 4) * 8;
    const uint32_t aoff = (uint32_t)(((wm * 32 + a_row) * PADK + a_kh) * 2);
    const int b_row = ((lane >> 4) << 3) + (lane & 7);
    const int b_kh  = ((lane >> 3) & 1) * 8;
    const uint32_t boff = (uint32_t)(((wn * 64 + b_row) * PADK + b_kh) * 2);

    float acc[2][8][4];
    #pragma unroll
    for (int i = 0; i < 2; i++)
        #pragma unroll
        for (int j = 0; j < 8; j++)
            #pragma unroll
            for (int q = 0; q < 4; q++) acc[i][j][q] = 0.f;

    const int ntiles = K / 32;

    auto fill = [&](int t) {
        const int k0 = t * 32;
        const uint32_t base = sm0 + (uint32_t)(t & 1) * BUFB;
        // A: 128 rows x 32 fp16 = 4 chunks/row (512 chunks)
        #pragma unroll
        for (int i = 0; i < 2; i++) {
            int s   = tid + 256 * i;
            int r   = s >> 2;
            int seg = s & 3;
            uint32_t off = (uint32_t)(r * (PADK * 2) + seg * 16);
            size_t go = (size_t)(row0 + r) * K + k0 + seg * 8;
            int sz = (row0 + r < M) ? 16 : 0;
            CPASYNC16Z(base + off, (const void*)(g_af16 + go), sz);
        }
        // Wh + Wl: 128 rows x 32 fp16 each
        #pragma unroll
        for (int i = 0; i < 2; i++) {
            int s   = tid + 256 * i;
            int r   = s >> 2;
            int seg = s & 3;
            uint32_t off = (uint32_t)(r * (PADK * 2) + seg * 16);
            size_t go = (size_t)(n0g + r) * K + k0 + seg * 8;
            CPASYNC16(base + ASUB + off,     (const void*)(g_wh + go));
            CPASYNC16(base + 2 * ASUB + off, (const void*)(g_wl + go));
        }
        CPCOMMIT();
    };

    fill(0);
    for (int t = 0; t < ntiles; t++) {
        CPWAIT0();
        __syncthreads();

        const uint32_t base = sm0 + (uint32_t)(t & 1) * BUFB;
        const uint32_t pA  = base + aoff;
        const uint32_t pWh = base + ASUB + boff;
        const uint32_t pWl = base + 2 * ASUB + boff;

        if (t + 1 < ntiles) fill(t + 1);

        HALF_TILE(0u);
        HALF_TILE(32u);
    }

    // ---- store C ----
    const int g   = lane >> 2;
    const int tig = lane & 3;
    #pragma unroll
    for (int mt = 0; mt < 2; mt++) {
        #pragma unroll
        for (int nt = 0; nt < 8; nt++) {
            int r = row0 + wm * 32 + mt * 16 + g;
            int c = n0g + wn * 64 + nt * 8 + 2 * tig;
            if (r < M)
                *reinterpret_cast<float2*>(&g_y[(size_t)r * 256 + c]) =
                    make_float2(acc[mt][nt][0], acc[mt][nt][1]);
            if (r + 8 < M)
                *reinterpret_cast<float2*>(&g_y[(size_t)(r + 8) * 256 + c]) =
                    make_float2(acc[mt][nt][2], acc[mt][nt][3]);
        }
    }
}

// ---------------- gather (bucketed) + combine ----------------
__global__ void gather_combine(const float* __restrict__ bias) {
    int warp = (blockIdx.x * blockDim.x + threadIdx.x) >> 5;
    int lane = threadIdx.x & 31;
    if (warp >= NN) return;
    int e0 = g_start[warp];
    int deg = g_deg[warp];
    int e1 = e0 + deg;
    float4 a0 = make_float4(0.f, 0.f, 0.f, 0.f);
    float4 a1 = make_float4(0.f, 0.f, 0.f, 0.f);
    float4 a2 = make_float4(0.f, 0.f, 0.f, 0.f);
    float4 a3 = make_float4(0.f, 0.f, 0.f, 0.f);
    int e = e0;
    for (; e + 4 <= e1; e += 4) {
        int s0 = g_csr[e], s1 = g_csr[e + 1], s2 = g_csr[e + 2], s3 = g_csr[e + 3];
        float4 v0 = reinterpret_cast<const float4*>(g_y + (size_t)s0 * 256)[lane];
        float4 v1 = reinterpret_cast<const float4*>(g_y + (size_t)s1 * 256)[lane];
        float4 v2 = reinterpret_cast<const float4*>(g_y + (size_t)s2 * 256)[lane];
        float4 v3 = reinterpret_cast<const float4*>(g_y + (size_t)s3 * 256)[lane];
        a0.x += v0.x; a0.y += v0.y; a0.z += v0.z; a0.w += v0.w;
        a1.x += v1.x; a1.y += v1.y; a1.z += v1.z; a1.w += v1.w;
        a2.x += v2.x; a2.y += v2.y; a2.z += v2.z; a2.w += v2.w;
        a3.x += v3.x; a3.y += v3.y; a3.z += v3.z; a3.w += v3.w;
    }
    for (; e < e1; e++) {
        int s = g_csr[e];
        float4 v = reinterpret_cast<const float4*>(g_y + (size_t)s * 256)[lane];
        a0.x += v.x; a0.y += v.y; a0.z += v.z; a0.w += v.w;
    }
    float4 acc;
    acc.x = (a0.x + a1.x) + (a2.x + a3.x);
    acc.y = (a0.y + a1.y) + (a2.y + a3.y);
    acc.z = (a0.z + a1.z) + (a2.z + a3.z);
    acc.w = (a0.w + a1.w) + (a2.w + a3.w);
    float invd = 1.f / fmaxf((float)deg, 1.f);
    float4 r  = reinterpret_cast<const float4*>(g_y + (size_t)warp * 256 + 128)[lane];
    float4 b4 = reinterpret_cast<const float4*>(bias)[lane];
    float4 o;
    o.x = acc.x * invd + r.x + b4.x;
    o.y = acc.y * invd + r.y + b4.y;
    o.z = acc.z * invd + r.z + b4.z;
    o.w = acc.w * invd + r.w + b4.w;
    reinterpret_cast<float4*>(g_hpre + (size_t)warp * HID)[lane] = o;
}

// ---------------- BatchNorm ----------------
__global__ void bn_stats_k() {
    int f = threadIdx.x;  // 128
    float s = 0.f, s2 = 0.f;
    for (int r = blockIdx.x; r < NN; r += 256) {
        float v = g_hpre[(size_t)r * HID + f];
        s += v; s2 += v * v;
    }
    g_part[blockIdx.x * 256 + f]       = s;
    g_part[blockIdx.x * 256 + 128 + f] = s2;
}

__global__ void reduce_stats_k(const float* __restrict__ gamma, const float* __restrict__ beta) {
    int f = threadIdx.x;  // 128
    float s = 0.f, s2 = 0.f;
    #pragma unroll 4
    for (int b = 0; b < 256; b++) {
        s  += g_part[b * 256 + f];
        s2 += g_part[b * 256 + 128 + f];
    }
    float mean = s * (1.f / NN);
    float var  = s2 * (1.f / NN) - mean * mean;
    float rstd = rsqrtf(var + BN_EPS);
    float g = gamma[f] * rstd;
    g_coef[f]       = g;
    g_coef[f + 128] = beta[f] - mean * g;
}

// mode 0: relu + write single fp16 (feeds next GEMM); mode 1: plain + write fp32 g_h
__global__ void bn_norm_k(int mode) {
    int f = threadIdx.x;
    float g = g_coef[f];
    float b = g_coef[f + 128];
    for (int r = blockIdx.x; r < NN; r += gridDim.x) {
        float v = g_hpre[(size_t)r * HID + f] * g + b;
        if (mode == 0) {
            v = fmaxf(v, 0.f);
            g_af16[(size_t)r * HID + f] = __float2half(v);
        } else {
            g_h[(size_t)r * HID + f] = v;
        }
    }
}

// ---------------- global max pool (batch is sorted) ----------------
#define POOL_CHUNK 512
__global__ void pool_max_k(const int* __restrict__ batch) {
    int f = threadIdx.x;  // 128
    int r0 = blockIdx.x * POOL_CHUNK;
    int r1 = min(r0 + POOL_CHUNK, NN);
    int cur = -1;
    float m = -3.4e38f;
    for (int r = r0; r < r1; r++) {
        int gi = batch[r];
        if (gi != cur) {
            if (cur >= 0) atomicMax(&g_pool[cur * HID + f], fenc(m));
            cur = gi;
            m = -3.4e38f;
        }
        m = fmaxf(m, g_h[(size_t)r * HID + f]);
    }
    if (cur >= 0) atomicMax(&g_pool[cur * HID + f], fenc(m));
}

// ---------------- final linear ----------------
__global__ void final_linear_k(const float* __restrict__ Wlin, const float* __restrict__ blin,
                               float* __restrict__ out) {
    __shared__ float sh[HID];
    int g = blockIdx.x, t = threadIdx.x;
    sh[t] = fdec(g_pool[g * HID + t]);
    __syncthreads();
    if (t < NCLS) {
        float a = blin[t];
        #pragma unroll 8
        for (int k = 0; k < HID; k++) a += sh[k] * Wlin[t * HID + k];
        out[g * NCLS + t] = a;
    }
}

// ---------------- launch ----------------
extern "C" void kernel_launch(void* const* d_in, const int* in_sizes, int n_in,
                              void* d_out, int out_size) {
    const float* x    = (const float*)d_in[0];
    const int*   src  = (const int*)d_in[1];
    const int*   dst  = src + NE;
    const int*   batch = (const int*)d_in[2];
    const float* W1l = (const float*)d_in[3];
    const float* b1  = (const float*)d_in[4];
    const float* W1r = (const float*)d_in[5];
    const float* g1  = (const float*)d_in[6];
    const float* be1 = (const float*)d_in[7];
    const float* W2l = (const float*)d_in[8];
    const float* b2  = (const float*)d_in[9];
    const float* W2r = (const float*)d_in[10];
    const float* g2  = (const float*)d_in[11];
    const float* be2 = (const float*)d_in[12];
    const float* W3l = (const float*)d_in[13];
    const float* b3  = (const float*)d_in[14];
    const float* W3r = (const float*)d_in[15];
    const float* g3  = (const float*)d_in[16];
    const float* be3 = (const float*)d_in[17];
    const float* Wlin = (const float*)d_in[18];
    const float* blin = (const float*)d_in[19];
    float* out = (float*)d_out;

    cudaFuncSetAttribute(gemm_mma, cudaFuncAttributeMaxDynamicSharedMemorySize, GEMM_SMEM);

    const int mblocks = (NN + 127) / 128;          // 391
    const int gblocks = mblocks * 2;
    const int gwarps  = (NN * 32 + 255) / 256;

    // ----- prologue + layer-1 GEMM (ncu capture slot = 4th launch) -----
    convert_w_k<<<(256 * IN_DIM + 255) / 256, 256>>>(W1l, W1r, IN_DIM);
    conv_x_k<<<(NN * IN_DIM / 4 + 255) / 256, 256>>>(x);
    zero_deg_k<<<(NN + 255) / 256, 256>>>();
    gemm_mma<<<gblocks, 256, GEMM_SMEM>>>(NN, IN_DIM);                       // profiled

    // CSR build
    hist_k<<<(NE + 255) / 256, 256>>>(dst);
    alloc_off_k<<<(NN + 255) / 256, 256>>>();
    fill_k<<<(NE + 255) / 256, 256>>>(src, dst);

    // ----- layer 1 tail -----
    gather_combine<<<gwarps, 256>>>(b1);
    bn_stats_k<<<256, 128>>>();
    reduce_stats_k<<<1, 128>>>(g1, be1);
    bn_norm_k<<<512, 128>>>(0);

    // ----- layer 2 -----
    convert_w_k<<<(256 * HID + 255) / 256, 256>>>(W2l, W2r, HID);
    gemm_mma<<<gblocks, 256, GEMM_SMEM>>>(NN, HID);
    gather_combine<<<gwarps, 256>>>(b2);
    bn_stats_k<<<256, 128>>>();
    reduce_stats_k<<<1, 128>>>(g2, be2);
    bn_norm_k<<<512, 128>>>(0);

    // ----- layer 3 -----
    convert_w_k<<<(256 * HID + 255) / 256, 256>>>(W3l, W3r, HID);
    gemm_mma<<<gblocks, 256, GEMM_SMEM>>>(NN, HID);
    gather_combine<<<gwarps, 256>>>(b3);
    bn_stats_k<<<256, 128>>>();
    reduce_stats_k<<<1, 128>>>(g3, be3);
    bn_norm_k<<<512, 128>>>(1);

    // ----- pool + head -----
    pool_max_k<<<(NN + POOL_CHUNK - 1) / POOL_CHUNK, 128>>>(batch);
    final_linear_k<<<NG, HID>>>(Wlin, blin, out);
}